// round 3
// baseline (speedup 1.0000x reference)
#include <cuda_runtime.h>
#include <cstdint>

// Problem constants (fixed by the dataset)
#define NN 100000
#define NE 1600000
#define F  32

// Scratch (no cudaMalloc allowed) — referenced directly from device code.
__device__ float g_deg[NN];
__device__ float g_h[(size_t)NN * F];

// ---------------------------------------------------------------------------
// Kernel 1: deg[v] = 1.0 (self-loop)
// ---------------------------------------------------------------------------
__global__ void k_init_deg(int n) {
    int i = blockIdx.x * blockDim.x + threadIdx.x;
    if (i < n) g_deg[i] = 1.0f;
}

// ---------------------------------------------------------------------------
// Kernel 2: deg[dst[e]] += 1 per edge  (indices arrive as int32)
// ---------------------------------------------------------------------------
__global__ void k_count(const int* __restrict__ dst, int e) {
    int i = blockIdx.x * blockDim.x + threadIdx.x;
    if (i < e) {
        int d = __ldg(dst + i);
        atomicAdd(&g_deg[d], 1.0f);
    }
}

// ---------------------------------------------------------------------------
// Kernel 3: h[v] = (x[v] * rsqrt(deg[v])) @ W^T ; also out[v] = h[v]
//           (out initialized with the self-loop contribution)
// One thread per node; W (32x32) staged in shared memory.
// ---------------------------------------------------------------------------
__global__ void k_project(const float* __restrict__ x,
                          const float* __restrict__ W,
                          float* __restrict__ out, int n) {
    __shared__ float sW[F][F];
    for (int i = threadIdx.x; i < F * F; i += blockDim.x)
        sW[i / F][i % F] = W[i];
    __syncthreads();

    int v = blockIdx.x * blockDim.x + threadIdx.x;
    if (v >= n) return;

    float s = rsqrtf(g_deg[v]);

    float xr[F];
    const float4* xp = reinterpret_cast<const float4*>(x + (size_t)v * F);
#pragma unroll
    for (int i = 0; i < F / 4; i++) {
        float4 q = __ldg(xp + i);
        xr[4 * i + 0] = q.x * s;
        xr[4 * i + 1] = q.y * s;
        xr[4 * i + 2] = q.z * s;
        xr[4 * i + 3] = q.w * s;
    }

    float hr[F];
#pragma unroll
    for (int o = 0; o < F; o++) {
        float acc = 0.0f;
#pragma unroll
        for (int i = 0; i < F; i++)
            acc = fmaf(xr[i], sW[o][i], acc);
        hr[o] = acc;
    }

    float4* hp = reinterpret_cast<float4*>(g_h + (size_t)v * F);
    float4* op = reinterpret_cast<float4*>(out + (size_t)v * F);
#pragma unroll
    for (int i = 0; i < F / 4; i++) {
        float4 q = make_float4(hr[4 * i], hr[4 * i + 1], hr[4 * i + 2], hr[4 * i + 3]);
        hp[i] = q;
        op[i] = q;
    }
}

// ---------------------------------------------------------------------------
// Kernel 4: edge scatter — warp per edge, lane per feature.
// out[dst] += h[src]   (coalesced 128B gather + 32-lane fp32 atomics)
// ---------------------------------------------------------------------------
__global__ void k_scatter(const int* __restrict__ src,
                          const int* __restrict__ dst,
                          float* __restrict__ out, int e) {
    int gtid = blockIdx.x * blockDim.x + threadIdx.x;
    int warp = gtid >> 5;
    int lane = gtid & 31;
    if (warp >= e) return;

    int s = __ldg(src + warp);
    int d = __ldg(dst + warp);
    float val = __ldg(g_h + (size_t)s * F + lane);
    atomicAdd(out + (size_t)d * F + lane, val);
}

// ---------------------------------------------------------------------------
// Kernel 5: out = relu(out * rsqrt(deg) + bias), vectorized float4
// ---------------------------------------------------------------------------
__global__ void k_final(float* __restrict__ out,
                        const float* __restrict__ bias, int n) {
    __shared__ float sb[F];
    if (threadIdx.x < F) sb[threadIdx.x] = bias[threadIdx.x];
    __syncthreads();

    int idx = blockIdx.x * blockDim.x + threadIdx.x;   // over n * (F/4)
    int total = n * (F / 4);
    if (idx >= total) return;

    int v = idx / (F / 4);
    int c = (idx % (F / 4)) * 4;
    float s = rsqrtf(g_deg[v]);

    float4 q = reinterpret_cast<float4*>(out)[idx];
    q.x = fmaxf(fmaf(q.x, s, sb[c + 0]), 0.0f);
    q.y = fmaxf(fmaf(q.y, s, sb[c + 1]), 0.0f);
    q.z = fmaxf(fmaf(q.z, s, sb[c + 2]), 0.0f);
    q.w = fmaxf(fmaf(q.w, s, sb[c + 3]), 0.0f);
    reinterpret_cast<float4*>(out)[idx] = q;
}

// ---------------------------------------------------------------------------
// Launch
// Inputs (metadata order): feature [N*32 f32], src [E i32], dst [E i32],
//                          W [32*32 f32], bias [32 f32]
// Output: [N*32] f32
// ---------------------------------------------------------------------------
extern "C" void kernel_launch(void* const* d_in, const int* in_sizes, int n_in,
                              void* d_out, int out_size) {
    const float* feature = (const float*)d_in[0];
    const int*   src     = (const int*)d_in[1];
    const int*   dst     = (const int*)d_in[2];
    const float* W       = (const float*)d_in[3];
    const float* bias    = (const float*)d_in[4];
    float*       out     = (float*)d_out;

    int n = in_sizes[0] / F;   // 100000
    int e = in_sizes[1];       // 1600000

    const int B = 256;

    k_init_deg<<<(n + B - 1) / B, B>>>(n);
    k_count<<<(e + B - 1) / B, B>>>(dst, e);
    k_project<<<(n + B - 1) / B, B>>>(feature, W, out, n);

    // warp per edge: 8 edges per 256-thread block
    int scatter_blocks = (e + (B / 32) - 1) / (B / 32);
    k_scatter<<<scatter_blocks, B>>>(src, dst, out, e);

    int total4 = n * (F / 4);
    k_final<<<(total4 + B - 1) / B, B>>>(out, bias, n);
}

// round 4
// speedup vs baseline: 1.8578x; 1.8578x over previous
#include <cuda_runtime.h>
#include <cstdint>

// Problem constants (fixed by the dataset)
#define NN 100000
#define NE 1600000
#define F  32

// Scratch (no cudaMalloc allowed) — referenced directly from device code.
__device__ float g_deg[NN];
__device__ float g_h[(size_t)NN * F];

// ---------------------------------------------------------------------------
// Kernel 1: deg[v] = 1.0 (self-loop)
// ---------------------------------------------------------------------------
__global__ void k_init_deg(int n) {
    int i = blockIdx.x * blockDim.x + threadIdx.x;
    if (i < n) g_deg[i] = 1.0f;
}

// ---------------------------------------------------------------------------
// Kernel 2: deg[dst[e]] += 1 per edge  (indices arrive as int32)
// ---------------------------------------------------------------------------
__global__ void k_count(const int* __restrict__ dst, int e) {
    int i = blockIdx.x * blockDim.x + threadIdx.x;
    if (i < e) {
        int d = __ldg(dst + i);
        atomicAdd(&g_deg[d], 1.0f);
    }
}

// ---------------------------------------------------------------------------
// Kernel 3: h[v] = (x[v] * rsqrt(deg[v])) @ W^T ; also out[v] = h[v]
//           (out initialized with the self-loop contribution)
// One thread per node; W (32x32) staged in shared memory.
// ---------------------------------------------------------------------------
__global__ void k_project(const float* __restrict__ x,
                          const float* __restrict__ W,
                          float* __restrict__ out, int n) {
    __shared__ float sW[F][F];
    for (int i = threadIdx.x; i < F * F; i += blockDim.x)
        sW[i / F][i % F] = W[i];
    __syncthreads();

    int v = blockIdx.x * blockDim.x + threadIdx.x;
    if (v >= n) return;

    float s = rsqrtf(g_deg[v]);

    float xr[F];
    const float4* xp = reinterpret_cast<const float4*>(x + (size_t)v * F);
#pragma unroll
    for (int i = 0; i < F / 4; i++) {
        float4 q = __ldg(xp + i);
        xr[4 * i + 0] = q.x * s;
        xr[4 * i + 1] = q.y * s;
        xr[4 * i + 2] = q.z * s;
        xr[4 * i + 3] = q.w * s;
    }

    float hr[F];
#pragma unroll
    for (int o = 0; o < F; o++) {
        float acc = 0.0f;
#pragma unroll
        for (int i = 0; i < F; i++)
            acc = fmaf(xr[i], sW[o][i], acc);
        hr[o] = acc;
    }

    float4* hp = reinterpret_cast<float4*>(g_h + (size_t)v * F);
    float4* op = reinterpret_cast<float4*>(out + (size_t)v * F);
#pragma unroll
    for (int i = 0; i < F / 4; i++) {
        float4 q = make_float4(hr[4 * i], hr[4 * i + 1], hr[4 * i + 2], hr[4 * i + 3]);
        hp[i] = q;
        op[i] = q;
    }
}

// ---------------------------------------------------------------------------
// Kernel 4: edge scatter — 8 threads per edge, one float4 quad per thread.
// Gather: one 16B __ldg.  Scatter: one red.global.add.v4.f32 (sm_90+).
// Cuts REDG instruction count 4x vs scalar atomicAdd (the round-3 binder).
// ---------------------------------------------------------------------------
__global__ void k_scatter(const int* __restrict__ src,
                          const int* __restrict__ dst,
                          float* __restrict__ out, int e) {
    int t = blockIdx.x * blockDim.x + threadIdx.x;
    int edge = t >> 3;           // 8 threads per edge
    if (edge >= e) return;
    int q = t & 7;               // feature quad 0..7

    int s = __ldg(src + edge);
    int d = __ldg(dst + edge);

    const float4* hp = reinterpret_cast<const float4*>(g_h + (size_t)s * F);
    float4 v = __ldg(hp + q);

    float* addr = out + (size_t)d * F + q * 4;
    asm volatile("red.global.add.v4.f32 [%0], {%1, %2, %3, %4};"
                 :: "l"(addr), "f"(v.x), "f"(v.y), "f"(v.z), "f"(v.w)
                 : "memory");
}

// ---------------------------------------------------------------------------
// Kernel 5: out = relu(out * rsqrt(deg) + bias), vectorized float4
// ---------------------------------------------------------------------------
__global__ void k_final(float* __restrict__ out,
                        const float* __restrict__ bias, int n) {
    __shared__ float sb[F];
    if (threadIdx.x < F) sb[threadIdx.x] = bias[threadIdx.x];
    __syncthreads();

    int idx = blockIdx.x * blockDim.x + threadIdx.x;   // over n * (F/4)
    int total = n * (F / 4);
    if (idx >= total) return;

    int v = idx / (F / 4);
    int c = (idx % (F / 4)) * 4;
    float s = rsqrtf(g_deg[v]);

    float4 q = reinterpret_cast<float4*>(out)[idx];
    q.x = fmaxf(fmaf(q.x, s, sb[c + 0]), 0.0f);
    q.y = fmaxf(fmaf(q.y, s, sb[c + 1]), 0.0f);
    q.z = fmaxf(fmaf(q.z, s, sb[c + 2]), 0.0f);
    q.w = fmaxf(fmaf(q.w, s, sb[c + 3]), 0.0f);
    reinterpret_cast<float4*>(out)[idx] = q;
}

// ---------------------------------------------------------------------------
// Launch
// Inputs (metadata order): feature [N*32 f32], src [E i32], dst [E i32],
//                          W [32*32 f32], bias [32 f32]
// Output: [N*32] f32
// ---------------------------------------------------------------------------
extern "C" void kernel_launch(void* const* d_in, const int* in_sizes, int n_in,
                              void* d_out, int out_size) {
    const float* feature = (const float*)d_in[0];
    const int*   src     = (const int*)d_in[1];
    const int*   dst     = (const int*)d_in[2];
    const float* W       = (const float*)d_in[3];
    const float* bias    = (const float*)d_in[4];
    float*       out     = (float*)d_out;

    int n = in_sizes[0] / F;   // 100000
    int e = in_sizes[1];       // 1600000

    const int B = 256;

    k_init_deg<<<(n + B - 1) / B, B>>>(n);
    k_count<<<(e + B - 1) / B, B>>>(dst, e);
    k_project<<<(n + B - 1) / B, B>>>(feature, W, out, n);

    // 8 threads per edge -> e*8 total threads
    long long sthreads = (long long)e * 8;
    int scatter_blocks = (int)((sthreads + B - 1) / B);
    k_scatter<<<scatter_blocks, B>>>(src, dst, out, e);

    int total4 = n * (F / 4);
    k_final<<<(total4 + B - 1) / B, B>>>(out, bias, n);
}